// round 5
// baseline (speedup 1.0000x reference)
#include <cuda_runtime.h>
#include <cstdint>

// ---------------------------------------------------------------------------
// EnsembleHead fused. B=1024, N=512, D_IN=30, H=64, 4H=256.
// R3: x-side gate preacts computed in 8-step chunks into SMEM (x-weights in
// SMEM, amortized); recurrence inner loop holds only 32 h-weight u64s in regs
// (no spills). Logit reduce moved off the barrier-critical path.
// ---------------------------------------------------------------------------

typedef unsigned long long ull;

#define Bsz   1024
#define Nseq  512
#define DIN   30
#define RPB   4
#define NBLK  (Bsz / RPB)   // 256
#define MH    32            // h k-pairs
#define CH    8             // chunk of timesteps

// prep outputs
__device__ ull   g_whh_pk[MH * 256];  // [m][j] packed (w_2m, w_2m+1)
__device__ float g_wxc[15 * 512];     // [dp][j*2+{0,1}] = W_comb[j][2dp..]
__device__ float g_bcomb[256];

// ---------------- helpers ----------------
__device__ __forceinline__ ull pkf2(float a, float b) {
    return (ull)__float_as_uint(a) | ((ull)__float_as_uint(b) << 32);
}
__device__ __forceinline__ ull pk2(float a) {
    ull r; asm("mov.b64 %0, {%1, %1};" : "=l"(r) : "f"(a)); return r;
}
__device__ __forceinline__ ull ffma2(ull a, ull b, ull c) {
    ull d;
    asm("fma.rn.f32x2 %0, %1, %2, %3;" : "=l"(d) : "l"(a), "l"(b), "l"(c));
    return d;
}
__device__ __forceinline__ float lo2(ull v) { return __uint_as_float((unsigned)v); }
__device__ __forceinline__ float hi2(ull v) { return __uint_as_float((unsigned)(v >> 32)); }
__device__ __forceinline__ float sum2(ull v) { return lo2(v) + hi2(v); }
__device__ __forceinline__ float ex2a(float x) {
    float r; asm("ex2.approx.f32 %0, %1;" : "=f"(r) : "f"(x)); return r;
}
__device__ __forceinline__ float rcpa(float x) {
    float r; asm("rcp.approx.f32 %0, %1;" : "=f"(r) : "f"(x)); return r;
}
__device__ __forceinline__ float sigm(float x) {
    return rcpa(1.0f + ex2a(-1.4426950408889634f * x));
}
__device__ __forceinline__ float tanh_(float x) {
    return fmaf(2.0f, rcpa(1.0f + ex2a(-2.8853900817779268f * x)), -1.0f);
}

// ---------------------------------------------------------------------------
// prep: fold FC into gate map; pack layouts.
// ---------------------------------------------------------------------------
__global__ void prep_kernel(const float* __restrict__ Wfc,
                            const float* __restrict__ bfc,
                            const float* __restrict__ Wih,
                            const float* __restrict__ Whh,
                            const float* __restrict__ bih,
                            const float* __restrict__ bhh)
{
    int j = threadIdx.x;

    float acc[DIN];
#pragma unroll
    for (int d = 0; d < DIN; ++d) acc[d] = 0.0f;
    float bs = bih[j] + bhh[j];

#pragma unroll 8
    for (int k = 0; k < 64; ++k) {
        float w = Wih[j * 64 + k];
        bs = fmaf(w, bfc[k], bs);
#pragma unroll
        for (int d = 0; d < DIN; ++d)
            acc[d] = fmaf(w, Wfc[k * DIN + d], acc[d]);
    }
    g_bcomb[j] = bs;
#pragma unroll
    for (int dp = 0; dp < 15; ++dp) {
        g_wxc[dp * 512 + 2 * j]     = acc[2 * dp];
        g_wxc[dp * 512 + 2 * j + 1] = acc[2 * dp + 1];
    }
#pragma unroll
    for (int m = 0; m < MH; ++m)
        g_whh_pk[m * 256 + j] = pkf2(Whh[j * 64 + 2 * m], Whh[j * 64 + 2 * m + 1]);
}

// ---------------------------------------------------------------------------
// shared layout (floats)
// ---------------------------------------------------------------------------
#define OFF_XG   0       // 8192 : xg[ti][r][j]   (ti*1024 + r*256 + j), bias folded
#define OFF_XS   8192    // 1920 : xs[buf][ti][d][r] (buf*960 + ti*120 + d*4 + r)
#define OFF_H    10112   // 256  : h[kp][r][par]  (kp*8 + r*2 + par)
#define OFF_G    10368   // 1024 : gates[r][j]
#define OFF_WXC  11392   // 7680 : x-weights [dp][2j..]
#define OFF_WL   19072   // 64
#define OFF_PART 19136   // 32   : logit partials [wid*4 + sublane]
#define OFF_LOG  19168   // 2048 : logits [r][512]
#define SMEM_FLOATS 21216
#define SMEM_BYTES  (SMEM_FLOATS * 4)

__global__ void __launch_bounds__(256, 2)
lstm_fused_kernel(const float* __restrict__ X,
                  const float* __restrict__ Wlast,
                  const float* __restrict__ blast,
                  float* __restrict__ out)
{
    extern __shared__ __align__(16) float s[];
    const int tid  = threadIdx.x;
    const int lane = tid & 31;
    const int wid  = tid >> 5;
    const int b0   = blockIdx.x * RPB;

    // ---- stage x-weights + misc into SMEM ----
    for (int i = tid; i < 7680; i += 256) s[OFF_WXC + i] = g_wxc[i];
    if (tid < 64) s[OFF_WL + tid] = Wlast[tid];
    s[OFF_H + tid] = 0.0f;

    // ---- h-weights into registers (64 regs) ----
    ull wh[MH];
#pragma unroll
    for (int m = 0; m < MH; ++m) wh[m] = g_whh_pk[m * 256 + tid];
    const float bias = g_bcomb[tid];
    const float blv  = blast[0];

    // ---- x prefetch role: thread < 120 owns (row, d) ----
    const int  prow = tid / DIN;
    const int  pd   = tid - prow * DIN;
    const bool px   = tid < RPB * DIN;
    const float* xp = X + (size_t)(b0 + prow) * (Nseq * DIN) + pd;
    const int  xsoff = pd * 4 + prow;
    if (px) {
#pragma unroll
        for (int i = 0; i < CH; ++i)
            s[OFF_XS + i * 120 + xsoff] = xp[i * DIN];
    }

    // ---- update role ----
    const int ur = tid >> 6, uk = tid & 63;
    const int goff = OFF_G + ur * 256 + uk;
    const int hoff = OFF_H + (uk >> 1) * 8 + ur * 2 + (uk & 1);
    const int q = tid >> 6;
    __syncthreads();
    const float wlk = s[OFF_WL + uk];
    float cc = 0.0f;

    for (int t = 0; t < Nseq; ++t) {
        const int ti = t & (CH - 1);

        if (ti == 0) {
            // ================= chunk boundary =================
            const int cbuf = (t >> 3) & 1;
            const bool pf = px && (t + CH < Nseq);
            float xv[CH];
            if (pf) {
#pragma unroll
                for (int i = 0; i < CH; ++i) xv[i] = xp[(t + CH + i) * DIN];
            }

            const float* xb = s + OFF_XS + cbuf * 960;
#pragma unroll
            for (int g2 = 0; g2 < 2; ++g2) {
                ull accA[4], accB[4];
#pragma unroll
                for (int i = 0; i < 4; ++i) { accA[i] = 0; accB[i] = 0; }
#pragma unroll
                for (int dp = 0; dp < 15; ++dp) {
                    float2 wv = *(const float2*)&s[OFF_WXC + dp * 512 + 2 * tid];
                    ull w0 = pk2(wv.x), w1 = pk2(wv.y);
#pragma unroll
                    for (int i = 0; i < 4; ++i) {
                        const int tt = g2 * 4 + i;
                        ulonglong2 u = *(const ulonglong2*)(xb + tt * 120 + 8 * dp);
                        ulonglong2 v = *(const ulonglong2*)(xb + tt * 120 + 8 * dp + 4);
                        accA[i] = ffma2(u.x, w0, accA[i]);
                        accB[i] = ffma2(u.y, w0, accB[i]);
                        accA[i] = ffma2(v.x, w1, accA[i]);
                        accB[i] = ffma2(v.y, w1, accB[i]);
                    }
                }
#pragma unroll
                for (int i = 0; i < 4; ++i) {
                    const int tt = g2 * 4 + i;
                    s[OFF_XG + tt * 1024 + 0 * 256 + tid] = lo2(accA[i]) + bias;
                    s[OFF_XG + tt * 1024 + 1 * 256 + tid] = hi2(accA[i]) + bias;
                    s[OFF_XG + tt * 1024 + 2 * 256 + tid] = lo2(accB[i]) + bias;
                    s[OFF_XG + tt * 1024 + 3 * 256 + tid] = hi2(accB[i]) + bias;
                }
            }

            if (pf) {
#pragma unroll
                for (int i = 0; i < CH; ++i)
                    s[OFF_XS + (cbuf ^ 1) * 960 + i * 120 + xsoff] = xv[i];
            }
            // no barrier: xg is same-thread produce/consume; xs consumed 8 steps later
        }

        // ================= recurrence step =================
        ull a0 = pkf2(s[OFF_XG + ti * 1024 +   0 + tid], 0.0f);
        ull a1 = pkf2(s[OFF_XG + ti * 1024 + 256 + tid], 0.0f);
        ull a2 = pkf2(s[OFF_XG + ti * 1024 + 512 + tid], 0.0f);
        ull a3 = pkf2(s[OFF_XG + ti * 1024 + 768 + tid], 0.0f);

        const ulonglong2* hq = (const ulonglong2*)(s + OFF_H);
#pragma unroll
        for (int m = 0; m < MH; ++m) {
            ulonglong2 pA = hq[2 * m];
            ulonglong2 pB = hq[2 * m + 1];
            ull w = wh[m];
            a0 = ffma2(pA.x, w, a0); a1 = ffma2(pA.y, w, a1);
            a2 = ffma2(pB.x, w, a2); a3 = ffma2(pB.y, w, a3);
        }

        float v0 = sum2(a0), v1 = sum2(a1), v2 = sum2(a2), v3 = sum2(a3);
        float g0, g1, g2, g3;
        if (q == 2) {
            g0 = tanh_(v0); g1 = tanh_(v1); g2 = tanh_(v2); g3 = tanh_(v3);
        } else {
            g0 = sigm(v0); g1 = sigm(v1); g2 = sigm(v2); g3 = sigm(v3);
        }
        s[OFF_G + 0 * 256 + tid] = g0;
        s[OFF_G + 1 * 256 + tid] = g1;
        s[OFF_G + 2 * 256 + tid] = g2;
        s[OFF_G + 3 * 256 + tid] = g3;

        __syncthreads();   // gates ready

        // combine previous step's logit partials (off the hot path: 4 threads)
        if (t > 0 && tid < RPB) {
            float acc = blv;
#pragma unroll
            for (int i = 0; i < 8; ++i) acc += s[OFF_PART + tid * 8 + i];
            s[OFF_LOG + tid * Nseq + (t - 1)] = acc;
        }

        // cell update
        float gi = s[goff];
        float gf = s[goff + 64];
        float gg = s[goff + 128];
        float go = s[goff + 192];
        cc = fmaf(gf, cc, gi * gg);
        float hv = go * tanh_(cc);
        s[hoff] = hv;

        __syncthreads();   // h ready

        // logit partial — after bar2, overlaps next step's matvec
        float p = hv * wlk;
        p += __shfl_down_sync(0xffffffffu, p, 16);
        p += __shfl_down_sync(0xffffffffu, p, 8);
        p += __shfl_down_sync(0xffffffffu, p, 4);
        if (lane < 4) s[OFF_PART + wid * 4 + lane] = p;
    }

    __syncthreads();
    if (tid < RPB) {
        float acc = blv;
#pragma unroll
        for (int i = 0; i < 8; ++i) acc += s[OFF_PART + tid * 8 + i];
        s[OFF_LOG + tid * Nseq + (Nseq - 1)] = acc;
    }
    __syncthreads();

    // ---- softmax over t: warp r handles row r ----
    if (wid < RPB) {
        float v[16];
#pragma unroll
        for (int i = 0; i < 16; ++i)
            v[i] = s[OFF_LOG + wid * Nseq + i * 32 + lane];
        float m = v[0];
#pragma unroll
        for (int i = 1; i < 16; ++i) m = fmaxf(m, v[i]);
        m = fmaxf(m, __shfl_xor_sync(0xffffffffu, m, 16));
        m = fmaxf(m, __shfl_xor_sync(0xffffffffu, m, 8));
        m = fmaxf(m, __shfl_xor_sync(0xffffffffu, m, 4));
        m = fmaxf(m, __shfl_xor_sync(0xffffffffu, m, 2));
        m = fmaxf(m, __shfl_xor_sync(0xffffffffu, m, 1));

        float e[16], sum = 0.0f;
#pragma unroll
        for (int i = 0; i < 16; ++i) {
            e[i] = ex2a((v[i] - m) * 1.4426950408889634f);
            sum += e[i];
        }
        sum += __shfl_xor_sync(0xffffffffu, sum, 16);
        sum += __shfl_xor_sync(0xffffffffu, sum, 8);
        sum += __shfl_xor_sync(0xffffffffu, sum, 4);
        sum += __shfl_xor_sync(0xffffffffu, sum, 2);
        sum += __shfl_xor_sync(0xffffffffu, sum, 1);
        const float inv = 1.0f / sum;

        float* orow = out + (size_t)(b0 + wid) * Nseq;
#pragma unroll
        for (int i = 0; i < 16; ++i)
            orow[i * 32 + lane] = e[i] * inv;
    }
}

// ---------------------------------------------------------------------------
extern "C" void kernel_launch(void* const* d_in, const int* in_sizes, int n_in,
                              void* d_out, int out_size) {
    const float* x     = (const float*)d_in[0];
    const float* Wfc   = (const float*)d_in[1];
    const float* bfc   = (const float*)d_in[2];
    const float* Wih   = (const float*)d_in[3];
    const float* Whh   = (const float*)d_in[4];
    const float* bih   = (const float*)d_in[5];
    const float* bhh   = (const float*)d_in[6];
    const float* Wlast = (const float*)d_in[7];
    const float* blast = (const float*)d_in[8];
    float* out = (float*)d_out;

    cudaFuncSetAttribute(lstm_fused_kernel,
                         cudaFuncAttributeMaxDynamicSharedMemorySize, SMEM_BYTES);

    prep_kernel<<<1, 256>>>(Wfc, bfc, Wih, Whh, bih, bhh);
    lstm_fused_kernel<<<NBLK, 256, SMEM_BYTES>>>(x, Wlast, blast, out);
}

// round 6
// speedup vs baseline: 1.0654x; 1.0654x over previous
#include <cuda_runtime.h>
#include <cstdint>

// ---------------------------------------------------------------------------
// EnsembleHead fused. B=1024, N=512, D_IN=30, H=64, 4H=256.
// R5: h-weights (32 u64) in registers ONLY; x-weights read per step from SMEM
// as direct LDS.64 f32x2 operands (no packing). No chunk phase -> no spills.
// RPB=4, grid=256x256, 2 CTAs/SM. Logit reduce off the barrier-critical path.
// ---------------------------------------------------------------------------

typedef unsigned long long ull;

#define Bsz   1024
#define Nseq  512
#define DIN   30
#define RPB   4
#define NBLK  (Bsz / RPB)   // 256
#define MX    15            // x d-pairs
#define MH    32            // h k-pairs

// prep outputs
__device__ ull   g_whh_pk[MH * 256];  // [m][j] packed (w_2m, w_2m+1)
__device__ float g_wxc[MX * 512];     // [dp][2j+{0,1}] = W_comb[j][2dp+{0,1}]
__device__ float g_bcomb[256];

// ---------------- helpers ----------------
__device__ __forceinline__ ull pkf2(float a, float b) {
    return (ull)__float_as_uint(a) | ((ull)__float_as_uint(b) << 32);
}
__device__ __forceinline__ ull ffma2(ull a, ull b, ull c) {
    ull d;
    asm("fma.rn.f32x2 %0, %1, %2, %3;" : "=l"(d) : "l"(a), "l"(b), "l"(c));
    return d;
}
__device__ __forceinline__ float sum2(ull v) {
    float lo, hi;
    asm("mov.b64 {%0, %1}, %2;" : "=f"(lo), "=f"(hi) : "l"(v));
    return lo + hi;
}
__device__ __forceinline__ float ex2a(float x) {
    float r; asm("ex2.approx.f32 %0, %1;" : "=f"(r) : "f"(x)); return r;
}
__device__ __forceinline__ float rcpa(float x) {
    float r; asm("rcp.approx.f32 %0, %1;" : "=f"(r) : "f"(x)); return r;
}
__device__ __forceinline__ float sigm(float x) {
    return rcpa(1.0f + ex2a(-1.4426950408889634f * x));
}
__device__ __forceinline__ float tanh_(float x) {
    return fmaf(2.0f, rcpa(1.0f + ex2a(-2.8853900817779268f * x)), -1.0f);
}

// ---------------------------------------------------------------------------
// prep: W_comb = Wih @ Wfc, b_comb = Wih@bfc + bih + bhh; pack pair layouts.
// ---------------------------------------------------------------------------
__global__ void prep_kernel(const float* __restrict__ Wfc,
                            const float* __restrict__ bfc,
                            const float* __restrict__ Wih,
                            const float* __restrict__ Whh,
                            const float* __restrict__ bih,
                            const float* __restrict__ bhh)
{
    int j = threadIdx.x;

    float acc[DIN];
#pragma unroll
    for (int d = 0; d < DIN; ++d) acc[d] = 0.0f;
    float bs = bih[j] + bhh[j];

#pragma unroll 8
    for (int k = 0; k < 64; ++k) {
        float w = Wih[j * 64 + k];
        bs = fmaf(w, bfc[k], bs);
#pragma unroll
        for (int d = 0; d < DIN; ++d)
            acc[d] = fmaf(w, Wfc[k * DIN + d], acc[d]);
    }
    g_bcomb[j] = bs;
#pragma unroll
    for (int dp = 0; dp < MX; ++dp) {
        g_wxc[dp * 512 + 2 * j]     = acc[2 * dp];
        g_wxc[dp * 512 + 2 * j + 1] = acc[2 * dp + 1];
    }
#pragma unroll
    for (int m = 0; m < MH; ++m)
        g_whh_pk[m * 256 + j] = pkf2(Whh[j * 64 + 2 * m], Whh[j * 64 + 2 * m + 1]);
}

// ---------------------------------------------------------------------------
// shared layout (floats); base is 16B aligned, offsets keep vector alignment
// ---------------------------------------------------------------------------
#define OFF_XS   0      // 240  : x stage [buf][dp][row][par], 2 x 120
#define OFF_H    240    // 256  : h [kp][row][par]
#define OFF_G    496    // 1024 : gates [row][j]
#define OFF_WXC  1520   // 7680 : x-weights [dp][2j..]
#define OFF_WL   9200   // 64
#define OFF_PART 9264   // 32   : logit partials [wid*4 + sub]
#define OFF_LOG  9296   // 2048 : logits [row][512]
#define SMEM_FLOATS 11344

__global__ void __launch_bounds__(256, 2)
lstm_fused_kernel(const float* __restrict__ X,
                  const float* __restrict__ Wlast,
                  const float* __restrict__ blast,
                  float* __restrict__ out)
{
    __shared__ __align__(16) float s[SMEM_FLOATS];
    const int tid  = threadIdx.x;
    const int lane = tid & 31;
    const int wid  = tid >> 5;
    const int b0   = blockIdx.x * RPB;

    // ---- stage x-weights + misc into SMEM ----
    for (int i = tid; i < MX * 512; i += 256) s[OFF_WXC + i] = g_wxc[i];
    if (tid < 64) s[OFF_WL + tid] = Wlast[tid];
    s[OFF_H + tid] = 0.0f;

    // ---- h-weights into registers (64 regs) ----
    ull wh[MH];
#pragma unroll
    for (int m = 0; m < MH; ++m) wh[m] = g_whh_pk[m * 256 + tid];
    const float bias = g_bcomb[tid];
    const float blv  = blast[0];

    // ---- x prefetch role: thread < 120 owns (row, d) ----
    const int  prow = tid / DIN;
    const int  pd   = tid - prow * DIN;
    const bool px   = tid < RPB * DIN;
    const float* xp = X + (size_t)(b0 + prow) * (Nseq * DIN) + pd;
    const int  xsoff = (pd >> 1) * 8 + prow * 2 + (pd & 1);
    if (px) s[OFF_XS + xsoff] = xp[0];

    // ---- update role: thread = (row ur, hidden uk) ----
    const int ur = tid >> 6, uk = tid & 63;
    const int goff = OFF_G + ur * 256 + uk;
    const int hoff = OFF_H + (uk >> 1) * 8 + ur * 2 + (uk & 1);
    const int q = tid >> 6;   // gate quarter (warp-uniform)
    __syncthreads();
    const float wlk = s[OFF_WL + uk];
    float cc = 0.0f;

    const ull* wxp = (const ull*)(s + OFF_WXC);   // [dp*256 + j]

    for (int t = 0; t < Nseq; ++t) {
        const int buf = t & 1;

        // prefetch x(t+1)
        float xv = 0.0f;
        const bool pf = px && (t + 1 < Nseq);
        if (pf) xv = xp[(t + 1) * DIN];

        // ---- gate matvec: 4 rows, (even,odd)-k lanes packed ----
        ull a0 = 0, a1 = 0, a2 = 0, a3 = 0;

        const ulonglong2* xq = (const ulonglong2*)(s + OFF_XS + buf * 120);
#pragma unroll
        for (int dp = 0; dp < MX; ++dp) {
            ull w = wxp[dp * 256 + tid];      // LDS.64, direct f32x2 operand
            ulonglong2 pA = xq[2 * dp];       // rows 0,1
            ulonglong2 pB = xq[2 * dp + 1];   // rows 2,3
            a0 = ffma2(pA.x, w, a0); a1 = ffma2(pA.y, w, a1);
            a2 = ffma2(pB.x, w, a2); a3 = ffma2(pB.y, w, a3);
        }
        const ulonglong2* hq = (const ulonglong2*)(s + OFF_H);
#pragma unroll
        for (int m = 0; m < MH; ++m) {
            ull w = wh[m];
            ulonglong2 pA = hq[2 * m];
            ulonglong2 pB = hq[2 * m + 1];
            a0 = ffma2(pA.x, w, a0); a1 = ffma2(pA.y, w, a1);
            a2 = ffma2(pB.x, w, a2); a3 = ffma2(pB.y, w, a3);
        }

        // stage next x into the other buffer
        if (pf) s[OFF_XS + (buf ^ 1) * 120 + xsoff] = xv;

        // ---- activation (warp-uniform branch) ----
        float v0 = sum2(a0) + bias;
        float v1 = sum2(a1) + bias;
        float v2 = sum2(a2) + bias;
        float v3 = sum2(a3) + bias;
        float g0, g1, g2, g3;
        if (q == 2) {
            g0 = tanh_(v0); g1 = tanh_(v1); g2 = tanh_(v2); g3 = tanh_(v3);
        } else {
            g0 = sigm(v0); g1 = sigm(v1); g2 = sigm(v2); g3 = sigm(v3);
        }
        s[OFF_G + 0 * 256 + tid] = g0;
        s[OFF_G + 1 * 256 + tid] = g1;
        s[OFF_G + 2 * 256 + tid] = g2;
        s[OFF_G + 3 * 256 + tid] = g3;

        __syncthreads();   // gates ready

        // combine previous step's logit partials (4 threads, off hot path)
        if (t > 0 && tid < RPB) {
            float acc = blv;
#pragma unroll
            for (int i = 0; i < 8; ++i) acc += s[OFF_PART + tid * 8 + i];
            s[OFF_LOG + tid * Nseq + (t - 1)] = acc;
        }

        // ---- cell update: thread = (ur, uk) ----
        float gi = s[goff];
        float gf = s[goff + 64];
        float gg = s[goff + 128];
        float go = s[goff + 192];
        cc = fmaf(gf, cc, gi * gg);
        float hv = go * tanh_(cc);
        s[hoff] = hv;

        __syncthreads();   // h ready

        // logit partial — after bar2, overlaps next step's matvec
        float p = hv * wlk;
        p += __shfl_down_sync(0xffffffffu, p, 16);
        p += __shfl_down_sync(0xffffffffu, p, 8);
        p += __shfl_down_sync(0xffffffffu, p, 4);
        if (lane < 4) s[OFF_PART + wid * 4 + lane] = p;
    }

    __syncthreads();
    if (tid < RPB) {
        float acc = blv;
#pragma unroll
        for (int i = 0; i < 8; ++i) acc += s[OFF_PART + tid * 8 + i];
        s[OFF_LOG + tid * Nseq + (Nseq - 1)] = acc;
    }
    __syncthreads();

    // ---- softmax over t: warp r handles row r ----
    if (wid < RPB) {
        float v[16];
#pragma unroll
        for (int i = 0; i < 16; ++i)
            v[i] = s[OFF_LOG + wid * Nseq + i * 32 + lane];
        float m = v[0];
#pragma unroll
        for (int i = 1; i < 16; ++i) m = fmaxf(m, v[i]);
        m = fmaxf(m, __shfl_xor_sync(0xffffffffu, m, 16));
        m = fmaxf(m, __shfl_xor_sync(0xffffffffu, m, 8));
        m = fmaxf(m, __shfl_xor_sync(0xffffffffu, m, 4));
        m = fmaxf(m, __shfl_xor_sync(0xffffffffu, m, 2));
        m = fmaxf(m, __shfl_xor_sync(0xffffffffu, m, 1));

        float e[16], sum = 0.0f;
#pragma unroll
        for (int i = 0; i < 16; ++i) {
            e[i] = ex2a((v[i] - m) * 1.4426950408889634f);
            sum += e[i];
        }
        sum += __shfl_xor_sync(0xffffffffu, sum, 16);
        sum += __shfl_xor_sync(0xffffffffu, sum, 8);
        sum += __shfl_xor_sync(0xffffffffu, sum, 4);
        sum += __shfl_xor_sync(0xffffffffu, sum, 2);
        sum += __shfl_xor_sync(0xffffffffu, sum, 1);
        const float inv = 1.0f / sum;

        float* orow = out + (size_t)(b0 + wid) * Nseq;
#pragma unroll
        for (int i = 0; i < 16; ++i)
            orow[i * 32 + lane] = e[i] * inv;
    }
}

// ---------------------------------------------------------------------------
extern "C" void kernel_launch(void* const* d_in, const int* in_sizes, int n_in,
                              void* d_out, int out_size) {
    const float* x     = (const float*)d_in[0];
    const float* Wfc   = (const float*)d_in[1];
    const float* bfc   = (const float*)d_in[2];
    const float* Wih   = (const float*)d_in[3];
    const float* Whh   = (const float*)d_in[4];
    const float* bih   = (const float*)d_in[5];
    const float* bhh   = (const float*)d_in[6];
    const float* Wlast = (const float*)d_in[7];
    const float* blast = (const float*)d_in[8];
    float* out = (float*)d_out;

    prep_kernel<<<1, 256>>>(Wfc, bfc, Wih, Whh, bih, bhh);
    lstm_fused_kernel<<<NBLK, 256>>>(x, Wlast, blast, out);
}